// round 4
// baseline (speedup 1.0000x reference)
#include <cuda_runtime.h>
#include <math.h>
#include <stdint.h>

// ---------------- scratch (no allocations allowed) ----------------
__device__ float g_attn[4ull * 4096ull * 4096ull];   // also holds XT inputs pre-attn
__device__ float g_FmT[4u * 4096u * 512u];
__device__ float g_GmT[4u * 4096u * 512u];
__device__ float g_HmT[4u * 4096u * 512u];
__device__ float g_Hcat[4ull * 1024ull * 4096ull];   // [Hm ; Hm^2], k-major
__device__ float g_Ccat[4ull * 4096ull * 1024ull];   // mean|second, [n][c]
__device__ float g_meanT[4u * 512u * 4096u];
__device__ float g_stdT [4u * 512u * 4096u];

__device__ __forceinline__ uint32_t smem_u32(const void* p) {
    uint32_t a;
    asm("{ .reg .u64 t; cvta.to.shared.u64 t, %1; cvt.u32.u64 %0, t; }" : "=r"(a) : "l"(p));
    return a;
}
__device__ __forceinline__ void cp16(uint32_t dst, const void* src) {
    asm volatile("cp.async.ca.shared.global [%0], [%1], 16;" :: "r"(dst), "l"(src));
}
__device__ __forceinline__ uint32_t tf32_hi(float v) {
    uint32_t h;
    asm("cvt.rna.tf32.f32 %0, %1;" : "=r"(h) : "f"(v));
    return h;
}

#define MMA_TF32(ACC, A0, A1, A2, A3, B0, B1)                                  \
    asm volatile(                                                              \
        "mma.sync.aligned.m16n8k8.row.col.f32.tf32.tf32.f32 "                  \
        "{%0,%1,%2,%3}, {%4,%5,%6,%7}, {%8,%9}, {%0,%1,%2,%3};"                \
        : "+f"((ACC)[0]), "+f"((ACC)[1]), "+f"((ACC)[2]), "+f"((ACC)[3])       \
        : "r"(A0), "r"(A1), "r"(A2), "r"(A3), "r"(B0), "r"(B1))

// ---------------- tf32 mma.sync GEMM (v2) ----------------
// C[b][m][n] = sum_k A[b][m][k] * B[b][n][k]  (+ bias[n])
// Block 128x256x32, 8 warps (2m x 4n), warp tile 64x64.
// PREC3: error-compensated tf32 (hi/lo split, 3 MMAs) for ~fp32 accuracy.
template<int PREC3, int HAS_BIAS>
__global__ __launch_bounds__(256) void mma_gemm(
    const float* __restrict__ A, const float* __restrict__ B,
    const float* __restrict__ bias, float* __restrict__ C,
    int M, int N, int K, size_t sA, size_t sB)
{
    extern __shared__ float sm[];
    const int tid = threadIdx.x, lane = tid & 31, wid = tid >> 5;
    const int b = blockIdx.z;
    const int n0 = blockIdx.x * 256, m0 = blockIdx.y * 128;
    const float* Ag = A + (size_t)b * sA + (size_t)m0 * K;
    const float* Bg = B + (size_t)b * sB + (size_t)n0 * K;

    const uint32_t s_base = smem_u32(sm);
    const int wm = (wid >> 2) * 64;     // 0 / 64
    const int wn = (wid & 3) * 64;      // 0,64,128,192

    float acc[4][8][4];
    #pragma unroll
    for (int i = 0; i < 4; i++)
        #pragma unroll
        for (int j = 0; j < 8; j++)
            #pragma unroll
            for (int r = 0; r < 4; r++) acc[i][j][r] = 0.f;

    const int NC = K / 32;

    // byte layout: A [2][128*144], B (at +36864) [2][256*144]
    auto stage = [&](int ch, int buf) {
        const float* Asrc = Ag + ch * 32;
        const float* Bsrc = Bg + ch * 32;
        uint32_t abase = s_base + buf * 18432u;
        uint32_t bbase = s_base + 36864u + buf * 36864u;
        #pragma unroll
        for (int it = 0; it < 4; it++) {
            int idx = tid + it * 256;
            int r = idx >> 3, f = idx & 7;
            cp16(abase + r * 144 + f * 16, Asrc + (size_t)r * K + f * 4);
        }
        #pragma unroll
        for (int it = 0; it < 8; it++) {
            int idx = tid + it * 256;
            int r = idx >> 3, f = idx & 7;
            cp16(bbase + r * 144 + f * 16, Bsrc + (size_t)r * K + f * 4);
        }
        asm volatile("cp.async.commit_group;" ::: "memory");
    };

    stage(0, 0);
    for (int ch = 0; ch < NC; ch++) {
        const int buf = ch & 1;
        if (ch + 1 < NC) {
            stage(ch + 1, buf ^ 1);
            asm volatile("cp.async.wait_group 1;" ::: "memory");
        } else {
            asm volatile("cp.async.wait_group 0;" ::: "memory");
        }
        __syncthreads();

        const float* Ab = sm + buf * 4608;            // floats
        const float* Bb = sm + 9216 + buf * 9216;

        #pragma unroll
        for (int k8 = 0; k8 < 32; k8 += 8) {
            const int kk = k8 + (lane & 3);
            // B fragments (8 n-tiles), hi/lo
            uint32_t bh[8][2], bl[8][2];
            #pragma unroll
            for (int jn = 0; jn < 8; jn++) {
                int c = wn + jn * 8 + (lane >> 2);
                float v0 = Bb[c * 36 + kk];
                float v1 = Bb[c * 36 + kk + 4];
                if (PREC3) {
                    bh[jn][0] = tf32_hi(v0); bl[jn][0] = __float_as_uint(v0 - __uint_as_float(bh[jn][0]));
                    bh[jn][1] = tf32_hi(v1); bl[jn][1] = __float_as_uint(v1 - __uint_as_float(bh[jn][1]));
                } else {
                    bh[jn][0] = __float_as_uint(v0);
                    bh[jn][1] = __float_as_uint(v1);
                }
            }
            #pragma unroll
            for (int im = 0; im < 4; im++) {
                int r = wm + im * 16 + (lane >> 2);
                float a0 = Ab[r * 36 + kk];
                float a1 = Ab[(r + 8) * 36 + kk];
                float a2 = Ab[r * 36 + kk + 4];
                float a3 = Ab[(r + 8) * 36 + kk + 4];
                uint32_t ah[4], al[4];
                if (PREC3) {
                    ah[0] = tf32_hi(a0); al[0] = __float_as_uint(a0 - __uint_as_float(ah[0]));
                    ah[1] = tf32_hi(a1); al[1] = __float_as_uint(a1 - __uint_as_float(ah[1]));
                    ah[2] = tf32_hi(a2); al[2] = __float_as_uint(a2 - __uint_as_float(ah[2]));
                    ah[3] = tf32_hi(a3); al[3] = __float_as_uint(a3 - __uint_as_float(ah[3]));
                } else {
                    ah[0] = __float_as_uint(a0); ah[1] = __float_as_uint(a1);
                    ah[2] = __float_as_uint(a2); ah[3] = __float_as_uint(a3);
                }
                #pragma unroll
                for (int jn = 0; jn < 8; jn++) {
                    if (PREC3) {
                        MMA_TF32(acc[im][jn], al[0], al[1], al[2], al[3], bh[jn][0], bh[jn][1]);
                        MMA_TF32(acc[im][jn], ah[0], ah[1], ah[2], ah[3], bl[jn][0], bl[jn][1]);
                    }
                    MMA_TF32(acc[im][jn], ah[0], ah[1], ah[2], ah[3], bh[jn][0], bh[jn][1]);
                }
            }
        }
        __syncthreads();
    }

    // epilogue: float2 stores
    float* Cb = C + (size_t)b * (size_t)M * (size_t)N;
    #pragma unroll
    for (int im = 0; im < 4; im++) {
        int r = m0 + wm + im * 16 + (lane >> 2);
        #pragma unroll
        for (int jn = 0; jn < 8; jn++) {
            int cc = n0 + wn + jn * 8 + (lane & 3) * 2;
            float b0 = 0.f, b1 = 0.f;
            if (HAS_BIAS) { b0 = __ldg(&bias[cc]); b1 = __ldg(&bias[cc + 1]); }
            *(float2*)(Cb + (size_t)r * N + cc) =
                make_float2(acc[im][jn][0] + b0, acc[im][jn][1] + b1);
            *(float2*)(Cb + (size_t)(r + 8) * N + cc) =
                make_float2(acc[im][jn][2] + b0, acc[im][jn][3] + b1);
        }
    }
}

// ---------------- transpose: src[b][R][C] -> dst[b][C][R] ----------------
__global__ void transpose_k(const float* __restrict__ src, float* __restrict__ dst, int R, int C)
{
    __shared__ float t[32][33];
    int b = blockIdx.z;
    const float* s = src + (size_t)b * R * C;
    float* d = dst + (size_t)b * R * C;
    int c0 = blockIdx.x * 32, r0 = blockIdx.y * 32;
    int tx = threadIdx.x, ty = threadIdx.y;
    #pragma unroll
    for (int k = 0; k < 4; k++)
        t[ty + k * 8][tx] = s[(size_t)(r0 + ty + k * 8) * C + c0 + tx];
    __syncthreads();
    #pragma unroll
    for (int k = 0; k < 4; k++)
        d[(size_t)(c0 + ty + k * 8) * R + r0 + tx] = t[tx][ty + k * 8];
}

// HmT [b][4096][512] -> Hcat [b][1024][4096]: rows 0..511 = Hm[c][n], 512..1023 = Hm^2
__global__ void transpose_sq(const float* __restrict__ src, float* __restrict__ dst)
{
    __shared__ float t[32][33];
    int b = blockIdx.z;
    const float* s = src + (size_t)b * 4096ull * 512ull;
    float* d = dst + (size_t)b * 1024ull * 4096ull;
    int c0 = blockIdx.x * 32, r0 = blockIdx.y * 32;
    int tx = threadIdx.x, ty = threadIdx.y;
    #pragma unroll
    for (int k = 0; k < 4; k++)
        t[ty + k * 8][tx] = s[(size_t)(r0 + ty + k * 8) * 512 + c0 + tx];
    __syncthreads();
    #pragma unroll
    for (int k = 0; k < 4; k++) {
        float v = t[tx][ty + k * 8];
        d[(size_t)(c0 + ty + k * 8) * 4096 + r0 + tx] = v;
        d[(size_t)(512 + c0 + ty + k * 8) * 4096 + r0 + tx] = v * v;
    }
}

// Ccat [b][n][1024] -> meanT/stdT [b][c][n]
__global__ void meanstd_transpose(const float* __restrict__ Ccat,
                                  float* __restrict__ meanT, float* __restrict__ stdT)
{
    __shared__ float tm[32][33], ts[32][33];
    int b = blockIdx.z;
    int c0 = blockIdx.x * 32, n0 = blockIdx.y * 32;
    const float* Cb = Ccat + (size_t)b * 4096ull * 1024ull;
    int tx = threadIdx.x, ty = threadIdx.y;
    #pragma unroll
    for (int k = 0; k < 4; k++) {
        int n = n0 + ty + k * 8;
        float mn = Cb[(size_t)n * 1024 + c0 + tx];
        float sc = Cb[(size_t)n * 1024 + 512 + c0 + tx];
        tm[ty + k * 8][tx] = mn;
        ts[ty + k * 8][tx] = sqrtf(fmaxf(sc - mn * mn, 0.f));
    }
    __syncthreads();
    size_t ob = (size_t)b * 512ull * 4096ull;
    #pragma unroll
    for (int k = 0; k < 4; k++) {
        int c = c0 + ty + k * 8;
        meanT[ob + (size_t)c * 4096 + n0 + tx] = tm[tx][ty + k * 8];
        stdT [ob + (size_t)c * 4096 + n0 + tx] = ts[tx][ty + k * 8];
    }
}

// ---------------- block reductions ----------------
__device__ __forceinline__ float block_reduce_max(float v, float* red) {
    #pragma unroll
    for (int o = 16; o > 0; o >>= 1) v = fmaxf(v, __shfl_xor_sync(0xffffffffu, v, o));
    int wid = threadIdx.x >> 5, lid = threadIdx.x & 31;
    if (lid == 0) red[wid] = v;
    __syncthreads();
    if (wid == 0) {
        v = (lid < 8) ? red[lid] : -1e30f;
        #pragma unroll
        for (int o = 4; o > 0; o >>= 1) v = fmaxf(v, __shfl_xor_sync(0xffffffffu, v, o));
        if (lid == 0) red[0] = v;
    }
    __syncthreads();
    float r = red[0];
    __syncthreads();
    return r;
}
__device__ __forceinline__ float block_reduce_sum(float v, float* red) {
    #pragma unroll
    for (int o = 16; o > 0; o >>= 1) v += __shfl_xor_sync(0xffffffffu, v, o);
    int wid = threadIdx.x >> 5, lid = threadIdx.x & 31;
    if (lid == 0) red[wid] = v;
    __syncthreads();
    if (wid == 0) {
        v = (lid < 8) ? red[lid] : 0.f;
        #pragma unroll
        for (int o = 4; o > 0; o >>= 1) v += __shfl_xor_sync(0xffffffffu, v, o);
        if (lid == 0) red[0] = v;
    }
    __syncthreads();
    float r = red[0];
    __syncthreads();
    return r;
}

// ---------------- softmax mix (per attn row, in place) ----------------
__global__ __launch_bounds__(256) void softmax_mix_kernel(
    float* __restrict__ attn, const float* __restrict__ w_mix)
{
    __shared__ float e1s[4096];
    __shared__ float e2s[4096];
    __shared__ float red[32];
    float* p = attn + (size_t)blockIdx.x * 4096;
    int tid = threadIdx.x;

    float lmax = -1e30f;
    for (int i = tid; i < 4096; i += 256) {
        float v = p[i];
        e1s[i] = v;
        lmax = fmaxf(lmax, v);
    }
    float m1 = block_reduce_max(lmax, red);
    float m2 = fmaxf(m1, 0.f);

    float z1 = 0.f, z2 = 0.f;
    for (int i = tid; i < 4096; i += 256) {
        float v = e1s[i];
        float e1 = __expf(v - m1);
        float e2 = __expf(fmaxf(v, 0.f) - m2);
        e1s[i] = e1; e2s[i] = e2;
        z1 += e1; z2 += e2;
    }
    float Z1 = block_reduce_sum(z1, red);
    float Z2 = block_reduce_sum(z2, red);

    float w0 = w_mix[0], w1 = w_mix[1];
    float ew0 = __expf(w0), ew1 = __expf(w1);
    float inv = 1.f / (ew0 + ew1);
    float iz1 = (ew0 * inv) / Z1;
    float iz2 = (ew1 * inv) / Z2;

    float za = 0.f;
    for (int i = tid; i < 4096; i += 256) {
        float A = e1s[i] * iz1 + e2s[i] * iz2;
        float e = __expf(A);   // A in (0,1]: no max-subtract needed
        e1s[i] = e;
        za += e;
    }
    float ZA = block_reduce_sum(za, red);
    float izA = 1.f / ZA;
    for (int i = tid; i < 4096; i += 256) p[i] = e1s[i] * izA;
}

// ---------------- finalize: out = stdT * mvn(content) + meanT ----------------
__global__ __launch_bounds__(256) void finalize_kernel(
    const float* __restrict__ content, const float* __restrict__ meanT,
    const float* __restrict__ stdT, float* __restrict__ out)
{
    __shared__ float red[32];
    int c = blockIdx.x, b = blockIdx.y;
    size_t off = ((size_t)b * 512 + c) * 4096;
    const float* x = content + off;
    int tid = threadIdx.x;

    float s = 0.f, ss = 0.f;
    for (int i = tid; i < 4096; i += 256) {
        float v = x[i];
        s += v; ss += v * v;
    }
    s = block_reduce_sum(s, red);
    ss = block_reduce_sum(ss, red);
    float mu = s * (1.f / 4096.f);
    float var = (ss - 4096.f * mu * mu) * (1.f / 4095.f);
    float rstd = rsqrtf(var + 1e-5f);

    for (int i = tid; i < 4096; i += 256)
        out[off + i] = stdT[off + i] * ((x[i] - mu) * rstd) + meanT[off + i];
}

// ---------------- launch ----------------
extern "C" void kernel_launch(void* const* d_in, const int* in_sizes, int n_in,
                              void* d_out, int out_size)
{
    const float* content     = (const float*)d_in[0];
    const float* style       = (const float*)d_in[1];
    const float* content_key = (const float*)d_in[2];
    const float* style_key   = (const float*)d_in[3];
    const float* f_w = (const float*)d_in[4];
    const float* f_b = (const float*)d_in[5];
    const float* g_w = (const float*)d_in[6];
    const float* g_b = (const float*)d_in[7];
    const float* h_w = (const float*)d_in[8];
    const float* h_b = (const float*)d_in[9];
    const float* w_mix = (const float*)d_in[10];
    float* out = (float*)d_out;

    float *attn, *FmT, *GmT, *HmT, *Hcat, *Ccat, *meanT, *stdT;
    cudaGetSymbolAddress((void**)&attn,  g_attn);
    cudaGetSymbolAddress((void**)&FmT,   g_FmT);
    cudaGetSymbolAddress((void**)&GmT,   g_GmT);
    cudaGetSymbolAddress((void**)&HmT,   g_HmT);
    cudaGetSymbolAddress((void**)&Hcat,  g_Hcat);
    cudaGetSymbolAddress((void**)&Ccat,  g_Ccat);
    cudaGetSymbolAddress((void**)&meanT, g_meanT);
    cudaGetSymbolAddress((void**)&stdT,  g_stdT);

    const int SMEM = 110592;  // A 2x18KB + B 2x36KB (stride 36 floats)
    cudaFuncSetAttribute(mma_gemm<1,1>, cudaFuncAttributeMaxDynamicSharedMemorySize, SMEM);
    cudaFuncSetAttribute(mma_gemm<1,0>, cudaFuncAttributeMaxDynamicSharedMemorySize, SMEM);
    cudaFuncSetAttribute(mma_gemm<0,0>, cudaFuncAttributeMaxDynamicSharedMemorySize, SMEM);

    // XT scratch lives in the (not-yet-used) attn buffer
    float* XT0 = attn;
    float* XT1 = attn + 8388608;     // 4*4096*512
    float* XT2 = attn + 16777216;

    // 1) transpose inputs [b][512][4096] -> [b][4096][512]
    transpose_k<<<dim3(128, 16, 4), dim3(32, 8)>>>(content_key, XT0, 512, 4096);
    transpose_k<<<dim3(128, 16, 4), dim3(32, 8)>>>(style_key,   XT1, 512, 4096);
    transpose_k<<<dim3(128, 16, 4), dim3(32, 8)>>>(style,       XT2, 512, 4096);

    // 2) convs (3xTF32, ~fp32-exact): FmT[n][o] = sum_c XT[n][c] * W[o][c] + b[o]
    mma_gemm<1,1><<<dim3(2, 32, 4), 256, SMEM>>>(XT0, f_w, f_b, FmT,
        4096, 512, 512, (size_t)4096 * 512, 0);
    mma_gemm<1,1><<<dim3(2, 32, 4), 256, SMEM>>>(XT1, g_w, g_b, GmT,
        4096, 512, 512, (size_t)4096 * 512, 0);
    mma_gemm<1,1><<<dim3(2, 32, 4), 256, SMEM>>>(XT2, h_w, h_b, HmT,
        4096, 512, 512, (size_t)4096 * 512, 0);

    // 3) Hcat[b][1024][4096] = [Hm[c][n] ; Hm[c][n]^2]
    transpose_sq<<<dim3(16, 128, 4), dim3(32, 8)>>>(HmT, Hcat);

    // 4) raw attention (3xTF32): attn[nc][ns] = sum_ck FmT[nc][ck] * GmT[ns][ck]
    mma_gemm<1,0><<<dim3(16, 32, 4), 256, SMEM>>>(FmT, GmT, nullptr, attn,
        4096, 4096, 512, (size_t)4096 * 512, (size_t)4096 * 512);

    // 5) triple-softmax mix, in place
    softmax_mix_kernel<<<16384, 256>>>(attn, w_mix);

    // 6) mean/second GEMM (1xTF32) vs Hcat -> Ccat[b][n][1024]
    mma_gemm<0,0><<<dim3(4, 32, 4), 256, SMEM>>>(attn, Hcat, nullptr, Ccat,
        4096, 1024, 4096, (size_t)4096 * 4096, (size_t)1024 * 4096);

    // 7) Ccat -> meanT/stdT [b][c][n]
    meanstd_transpose<<<dim3(16, 128, 4), dim3(32, 8)>>>(Ccat, meanT, stdT);

    // 8) finalize
    finalize_kernel<<<dim3(512, 4), 256>>>(content, meanT, stdT, out);
}

// round 5
// speedup vs baseline: 1.4516x; 1.4516x over previous
#include <cuda_runtime.h>
#include <cuda_bf16.h>
#include <cuda_fp16.h>
#include <math.h>
#include <stdint.h>

// ---------------- scratch (uint4 => 16B alignment for cp.async) ----------------
__device__ uint4 g_attn4 [16777216];   // fp32 attn  [4][4096][4096]
__device__ uint4 g_S4    [8388608];    // half  S    [4][4096][4096]
__device__ uint4 g_xth4  [3145728];    // bf16 XT hi, 3 inputs x [4][4096][512]
__device__ uint4 g_xtl4  [3145728];    // bf16 XT lo
__device__ uint4 g_wh4   [98304];      // bf16 W hi, 3 x [512][512]
__device__ uint4 g_wl4   [98304];
__device__ uint4 g_Fh4   [1048576];    // bf16 Fm hi [4][4096][512]
__device__ uint4 g_Fl4   [1048576];
__device__ uint4 g_Gh4   [1048576];
__device__ uint4 g_Gl4   [1048576];
__device__ uint4 g_HmT4  [2097152];    // fp32 Hm [4][4096][512] ([n][c])
__device__ uint4 g_Hcat4 [2097152];    // half Hcat [4][1024][4096]
__device__ uint4 g_Ccat4 [4194304];    // fp32 Ccat [4][4096][1024]
__device__ uint4 g_meanT4[2097152];    // fp32 [4][512][4096]
__device__ uint4 g_stdT4 [2097152];

// ---------------- helpers ----------------
__device__ __forceinline__ uint32_t smem_u32(const void* p) {
    uint32_t a;
    asm("{ .reg .u64 t; cvta.to.shared.u64 t, %1; cvt.u32.u64 %0, t; }" : "=r"(a) : "l"(p));
    return a;
}
__device__ __forceinline__ void cp16(uint32_t dst, const void* src) {
    asm volatile("cp.async.ca.shared.global [%0], [%1], 16;" :: "r"(dst), "l"(src));
}
__device__ __forceinline__ uint32_t lds32(uint32_t a) {
    uint32_t v;
    asm("ld.shared.b32 %0, [%1];" : "=r"(v) : "r"(a));
    return v;
}
__device__ __forceinline__ void mma16(float* d, const uint32_t* a, const uint32_t* b,
                                      const __nv_bfloat16*) {
    asm volatile("mma.sync.aligned.m16n8k16.row.col.f32.bf16.bf16.f32 "
        "{%0,%1,%2,%3}, {%4,%5,%6,%7}, {%8,%9}, {%0,%1,%2,%3};"
        : "+f"(d[0]), "+f"(d[1]), "+f"(d[2]), "+f"(d[3])
        : "r"(a[0]), "r"(a[1]), "r"(a[2]), "r"(a[3]), "r"(b[0]), "r"(b[1]));
}
__device__ __forceinline__ void mma16(float* d, const uint32_t* a, const uint32_t* b,
                                      const half*) {
    asm volatile("mma.sync.aligned.m16n8k16.row.col.f32.f16.f16.f32 "
        "{%0,%1,%2,%3}, {%4,%5,%6,%7}, {%8,%9}, {%0,%1,%2,%3};"
        : "+f"(d[0]), "+f"(d[1]), "+f"(d[2]), "+f"(d[3])
        : "r"(a[0]), "r"(a[1]), "r"(a[2]), "r"(a[3]), "r"(b[0]), "r"(b[1]));
}

// ---------------- GEMM: C[b][m][n] = sum_k A[m][k]*B[n][k] (+bias[n]) ----------------
// Operands: hi/lo 16-bit pairs (TERMS=3: AhBh+AlBh+AhBl) or hi only (TERMS=1).
// Block 128x128xk32, 8 warps (2m x 4n), warp tile 64x32, cp.async double buffer.
// OUT_SPLIT=1: write bf16 hi/lo arrays; else fp32.
template<typename T, int TERMS, int OUT_SPLIT, int HAS_BIAS>
__global__ __launch_bounds__(256, 2) void gemm16(
    const T* __restrict__ Ah, const T* __restrict__ Al,
    const T* __restrict__ Bh, const T* __restrict__ Bl,
    const float* __restrict__ bias,
    float* __restrict__ Cf, T* __restrict__ Ch, T* __restrict__ Cl,
    int M, int N, int K, size_t sA, size_t sB)
{
    extern __shared__ char smem[];
    const int tid = threadIdx.x, lane = tid & 31, wid = tid >> 5;
    const int b = blockIdx.z;
    const int n0 = blockIdx.x * 128, m0 = blockIdx.y * 128;
    const T* Agh = Ah + (size_t)b * sA + (size_t)m0 * K;
    const T* Bgh = Bh + (size_t)b * sB + (size_t)n0 * K;
    const T* Agl = (TERMS == 3) ? (Al + (size_t)b * sA + (size_t)m0 * K) : nullptr;
    const T* Bgl = (TERMS == 3) ? (Bl + (size_t)b * sB + (size_t)n0 * K) : nullptr;

    const uint32_t sb = smem_u32(smem);
    constexpr uint32_t TL = 128u * 80u;               // 10240 B per tile (32 k x 2B, stride 80)
    constexpr uint32_t BUF = (TERMS == 3 ? 4u : 2u) * TL;

    const int wm = (wid >> 2) * 64, wn = (wid & 3) * 32;

    float acc[4][4][4];
    #pragma unroll
    for (int i = 0; i < 4; i++)
        #pragma unroll
        for (int j = 0; j < 4; j++)
            #pragma unroll
            for (int r = 0; r < 4; r++) acc[i][j][r] = 0.f;

    auto stage = [&](int ch, int buf) {
        uint32_t base = sb + buf * BUF;
        #pragma unroll
        for (int it = 0; it < 2; it++) {
            int idx = tid + it * 256;
            int r = idx >> 2, f = idx & 3;
            uint32_t off = r * 80 + f * 16;
            size_t go = (size_t)r * K + ch * 32 + f * 8;
            cp16(base + off, Agh + go);
            cp16(base + TL + off, Bgh + go);
            if (TERMS == 3) {
                cp16(base + 2 * TL + off, Agl + go);
                cp16(base + 3 * TL + off, Bgl + go);
            }
        }
        asm volatile("cp.async.commit_group;" ::: "memory");
    };

    const int NC = K / 32;
    stage(0, 0);
    for (int ch = 0; ch < NC; ch++) {
        const int buf = ch & 1;
        if (ch + 1 < NC) {
            stage(ch + 1, buf ^ 1);
            asm volatile("cp.async.wait_group 1;" ::: "memory");
        } else {
            asm volatile("cp.async.wait_group 0;" ::: "memory");
        }
        __syncthreads();

        const uint32_t ab = sb + buf * BUF;   // A hi
        const uint32_t bb = ab + TL;          // B hi

        #pragma unroll
        for (int k16 = 0; k16 < 2; k16++) {
            const uint32_t kb = k16 * 32 + (lane & 3) * 4;   // byte offset in row
            uint32_t bhf[4][2], blf[4][2];
            #pragma unroll
            for (int jn = 0; jn < 4; jn++) {
                uint32_t rb = (uint32_t)(wn + jn * 8 + (lane >> 2)) * 80 + kb;
                bhf[jn][0] = lds32(bb + rb);
                bhf[jn][1] = lds32(bb + rb + 16);
                if (TERMS == 3) {
                    blf[jn][0] = lds32(bb + 2 * TL + rb);
                    blf[jn][1] = lds32(bb + 2 * TL + rb + 16);
                }
            }
            #pragma unroll
            for (int im = 0; im < 4; im++) {
                uint32_t r0b = (uint32_t)(wm + im * 16 + (lane >> 2)) * 80 + kb;
                uint32_t af[4];
                af[0] = lds32(ab + r0b);
                af[1] = lds32(ab + r0b + 8 * 80);
                af[2] = lds32(ab + r0b + 16);
                af[3] = lds32(ab + r0b + 8 * 80 + 16);
                #pragma unroll
                for (int jn = 0; jn < 4; jn++) {
                    mma16(acc[im][jn], af, bhf[jn], (const T*)nullptr);
                    if (TERMS == 3) mma16(acc[im][jn], af, blf[jn], (const T*)nullptr);
                }
                if (TERMS == 3) {
                    uint32_t alf[4];
                    alf[0] = lds32(ab + 2 * TL + r0b);
                    alf[1] = lds32(ab + 2 * TL + r0b + 8 * 80);
                    alf[2] = lds32(ab + 2 * TL + r0b + 16);
                    alf[3] = lds32(ab + 2 * TL + r0b + 8 * 80 + 16);
                    #pragma unroll
                    for (int jn = 0; jn < 4; jn++)
                        mma16(acc[im][jn], alf, bhf[jn], (const T*)nullptr);
                }
            }
        }
        __syncthreads();
    }

    // epilogue
    #pragma unroll
    for (int im = 0; im < 4; im++) {
        int r = m0 + wm + im * 16 + (lane >> 2);
        #pragma unroll
        for (int jn = 0; jn < 4; jn++) {
            int cc = n0 + wn + jn * 8 + (lane & 3) * 2;
            float b0 = 0.f, b1 = 0.f;
            if (HAS_BIAS) { b0 = __ldg(&bias[cc]); b1 = __ldg(&bias[cc + 1]); }
            float v00 = acc[im][jn][0] + b0, v01 = acc[im][jn][1] + b1;
            float v10 = acc[im][jn][2] + b0, v11 = acc[im][jn][3] + b1;
            size_t o0 = (size_t)b * (size_t)M * N + (size_t)r * N + cc;
            size_t o1 = o0 + (size_t)8 * N;
            if constexpr (OUT_SPLIT) {
                __nv_bfloat16 h00 = __float2bfloat16_rn(v00), h01 = __float2bfloat16_rn(v01);
                __nv_bfloat16 h10 = __float2bfloat16_rn(v10), h11 = __float2bfloat16_rn(v11);
                *(__nv_bfloat162*)((__nv_bfloat16*)Ch + o0) = __nv_bfloat162(h00, h01);
                *(__nv_bfloat162*)((__nv_bfloat16*)Ch + o1) = __nv_bfloat162(h10, h11);
                *(__nv_bfloat162*)((__nv_bfloat16*)Cl + o0) = __nv_bfloat162(
                    __float2bfloat16_rn(v00 - __bfloat162float(h00)),
                    __float2bfloat16_rn(v01 - __bfloat162float(h01)));
                *(__nv_bfloat162*)((__nv_bfloat16*)Cl + o1) = __nv_bfloat162(
                    __float2bfloat16_rn(v10 - __bfloat162float(h10)),
                    __float2bfloat16_rn(v11 - __bfloat162float(h11)));
            } else {
                *(float2*)(Cf + o0) = make_float2(v00, v01);
                *(float2*)(Cf + o1) = make_float2(v10, v11);
            }
        }
    }
}

// ---------------- transpose+split: src fp32 [b][512][4096] -> hi/lo bf16 [b][4096][512] ----------------
__global__ void transpose_split(const float* __restrict__ src,
                                __nv_bfloat16* __restrict__ dh, __nv_bfloat16* __restrict__ dl)
{
    __shared__ float t[32][33];
    int b = blockIdx.z;
    const float* s = src + (size_t)b * 512ull * 4096ull;
    size_t dbo = (size_t)b * 512ull * 4096ull;
    int c0 = blockIdx.x * 32, r0 = blockIdx.y * 32;
    int tx = threadIdx.x, ty = threadIdx.y;
    #pragma unroll
    for (int k = 0; k < 4; k++)
        t[ty + k * 8][tx] = s[(size_t)(r0 + ty + k * 8) * 4096 + c0 + tx];
    __syncthreads();
    #pragma unroll
    for (int k = 0; k < 4; k++) {
        float v = t[tx][ty + k * 8];
        size_t o = dbo + (size_t)(c0 + ty + k * 8) * 512 + r0 + tx;
        __nv_bfloat16 h = __float2bfloat16_rn(v);
        dh[o] = h;
        dl[o] = __float2bfloat16_rn(v - __bfloat162float(h));
    }
}

// ---------------- weight split: fp32 [n] -> hi/lo bf16 ----------------
__global__ void weight_split(const float* __restrict__ w,
                             __nv_bfloat16* __restrict__ wh, __nv_bfloat16* __restrict__ wl, int n)
{
    int i = blockIdx.x * 256 + threadIdx.x;
    if (i < n) {
        float v = w[i];
        __nv_bfloat16 h = __float2bfloat16_rn(v);
        wh[i] = h;
        wl[i] = __float2bfloat16_rn(v - __bfloat162float(h));
    }
}

// ---------------- HmT fp32 [b][4096(n)][512(c)] -> Hcat half [b][1024][4096]: [H ; H^2] ----------------
__global__ void transpose_sq_half(const float* __restrict__ src, half* __restrict__ dst)
{
    __shared__ float t[32][33];
    int b = blockIdx.z;
    const float* s = src + (size_t)b * 4096ull * 512ull;
    half* d = dst + (size_t)b * 1024ull * 4096ull;
    int c0 = blockIdx.x * 32, n0 = blockIdx.y * 32;
    int tx = threadIdx.x, ty = threadIdx.y;
    #pragma unroll
    for (int k = 0; k < 4; k++)
        t[ty + k * 8][tx] = s[(size_t)(n0 + ty + k * 8) * 512 + c0 + tx];
    __syncthreads();
    #pragma unroll
    for (int k = 0; k < 4; k++) {
        float v = t[tx][ty + k * 8];   // H[c0+ty+k8][n0+tx]
        d[(size_t)(c0 + ty + k * 8) * 4096 + n0 + tx] = __float2half_rn(v);
        d[(size_t)(512 + c0 + ty + k * 8) * 4096 + n0 + tx] = __float2half_rn(v * v);
    }
}

// Ccat [b][n][1024] -> meanT/stdT [b][c][n]
__global__ void meanstd_transpose(const float* __restrict__ Ccat,
                                  float* __restrict__ meanT, float* __restrict__ stdT)
{
    __shared__ float tm[32][33], ts[32][33];
    int b = blockIdx.z;
    int c0 = blockIdx.x * 32, n0 = blockIdx.y * 32;
    const float* Cb = Ccat + (size_t)b * 4096ull * 1024ull;
    int tx = threadIdx.x, ty = threadIdx.y;
    #pragma unroll
    for (int k = 0; k < 4; k++) {
        int n = n0 + ty + k * 8;
        float mn = Cb[(size_t)n * 1024 + c0 + tx];
        float sc = Cb[(size_t)n * 1024 + 512 + c0 + tx];
        tm[ty + k * 8][tx] = mn;
        ts[ty + k * 8][tx] = sqrtf(fmaxf(sc - mn * mn, 0.f));
    }
    __syncthreads();
    size_t ob = (size_t)b * 512ull * 4096ull;
    #pragma unroll
    for (int k = 0; k < 4; k++) {
        int c = c0 + ty + k * 8;
        meanT[ob + (size_t)c * 4096 + n0 + tx] = tm[tx][ty + k * 8];
        stdT [ob + (size_t)c * 4096 + n0 + tx] = ts[tx][ty + k * 8];
    }
}

// ---------------- block reductions ----------------
__device__ __forceinline__ float block_reduce_max(float v, float* red) {
    #pragma unroll
    for (int o = 16; o > 0; o >>= 1) v = fmaxf(v, __shfl_xor_sync(0xffffffffu, v, o));
    int wid = threadIdx.x >> 5, lid = threadIdx.x & 31;
    if (lid == 0) red[wid] = v;
    __syncthreads();
    if (wid == 0) {
        v = (lid < 8) ? red[lid] : -1e30f;
        #pragma unroll
        for (int o = 4; o > 0; o >>= 1) v = fmaxf(v, __shfl_xor_sync(0xffffffffu, v, o));
        if (lid == 0) red[0] = v;
    }
    __syncthreads();
    float r = red[0];
    __syncthreads();
    return r;
}
__device__ __forceinline__ float block_reduce_sum(float v, float* red) {
    #pragma unroll
    for (int o = 16; o > 0; o >>= 1) v += __shfl_xor_sync(0xffffffffu, v, o);
    int wid = threadIdx.x >> 5, lid = threadIdx.x & 31;
    if (lid == 0) red[wid] = v;
    __syncthreads();
    if (wid == 0) {
        v = (lid < 8) ? red[lid] : 0.f;
        #pragma unroll
        for (int o = 4; o > 0; o >>= 1) v += __shfl_xor_sync(0xffffffffu, v, o);
        if (lid == 0) red[0] = v;
    }
    __syncthreads();
    float r = red[0];
    __syncthreads();
    return r;
}

// ---------------- softmax mix: fp32 in -> half S out ----------------
__global__ __launch_bounds__(256) void softmax_mix_kernel(
    const float* __restrict__ attn, half* __restrict__ S, const float* __restrict__ w_mix)
{
    __shared__ float e1s[4096];
    __shared__ float e2s[4096];
    __shared__ float red[32];
    const float* p = attn + (size_t)blockIdx.x * 4096;
    half* q = S + (size_t)blockIdx.x * 4096;
    int tid = threadIdx.x;

    float lmax = -1e30f;
    for (int i = tid; i < 4096; i += 256) {
        float v = p[i];
        e1s[i] = v;
        lmax = fmaxf(lmax, v);
    }
    float m1 = block_reduce_max(lmax, red);
    float m2 = fmaxf(m1, 0.f);

    float z1 = 0.f, z2 = 0.f;
    for (int i = tid; i < 4096; i += 256) {
        float v = e1s[i];
        float e1 = __expf(v - m1);
        float e2 = __expf(fmaxf(v, 0.f) - m2);
        e1s[i] = e1; e2s[i] = e2;
        z1 += e1; z2 += e2;
    }
    float Z1 = block_reduce_sum(z1, red);
    float Z2 = block_reduce_sum(z2, red);

    float ew0 = __expf(w_mix[0]), ew1 = __expf(w_mix[1]);
    float inv = 1.f / (ew0 + ew1);
    float iz1 = (ew0 * inv) / Z1;
    float iz2 = (ew1 * inv) / Z2;

    float za = 0.f;
    for (int i = tid; i < 4096; i += 256) {
        float A = e1s[i] * iz1 + e2s[i] * iz2;
        float e = __expf(A);   // A in (0,1]
        e1s[i] = e;
        za += e;
    }
    float ZA = block_reduce_sum(za, red);
    float izA = 1.f / ZA;
    for (int i = tid; i < 4096; i += 256)
        q[i] = __float2half_rn(e1s[i] * izA);
}

// ---------------- finalize: out = stdT * mvn(content) + meanT ----------------
__global__ __launch_bounds__(256) void finalize_kernel(
    const float* __restrict__ content, const float* __restrict__ meanT,
    const float* __restrict__ stdT, float* __restrict__ out)
{
    __shared__ float red[32];
    int c = blockIdx.x, b = blockIdx.y;
    size_t off = ((size_t)b * 512 + c) * 4096;
    const float* x = content + off;
    int tid = threadIdx.x;

    float s = 0.f, ss = 0.f;
    for (int i = tid; i < 4096; i += 256) {
        float v = x[i];
        s += v; ss += v * v;
    }
    s = block_reduce_sum(s, red);
    ss = block_reduce_sum(ss, red);
    float mu = s * (1.f / 4096.f);
    float var = (ss - 4096.f * mu * mu) * (1.f / 4095.f);
    float rstd = rsqrtf(var + 1e-5f);

    for (int i = tid; i < 4096; i += 256)
        out[off + i] = stdT[off + i] * ((x[i] - mu) * rstd) + meanT[off + i];
}

// ---------------- launch ----------------
extern "C" void kernel_launch(void* const* d_in, const int* in_sizes, int n_in,
                              void* d_out, int out_size)
{
    const float* content     = (const float*)d_in[0];
    const float* style       = (const float*)d_in[1];
    const float* content_key = (const float*)d_in[2];
    const float* style_key   = (const float*)d_in[3];
    const float* f_w = (const float*)d_in[4];
    const float* f_b = (const float*)d_in[5];
    const float* g_w = (const float*)d_in[6];
    const float* g_b = (const float*)d_in[7];
    const float* h_w = (const float*)d_in[8];
    const float* h_b = (const float*)d_in[9];
    const float* w_mix = (const float*)d_in[10];
    float* out = (float*)d_out;

    typedef __nv_bfloat16 bf16;
    void *p;
    cudaGetSymbolAddress(&p, g_attn4);  float* attn = (float*)p;
    cudaGetSymbolAddress(&p, g_S4);     half*  S    = (half*)p;
    cudaGetSymbolAddress(&p, g_xth4);   bf16*  XTh  = (bf16*)p;
    cudaGetSymbolAddress(&p, g_xtl4);   bf16*  XTl  = (bf16*)p;
    cudaGetSymbolAddress(&p, g_wh4);    bf16*  Wh   = (bf16*)p;
    cudaGetSymbolAddress(&p, g_wl4);    bf16*  Wl   = (bf16*)p;
    cudaGetSymbolAddress(&p, g_Fh4);    bf16*  Fh   = (bf16*)p;
    cudaGetSymbolAddress(&p, g_Fl4);    bf16*  Fl   = (bf16*)p;
    cudaGetSymbolAddress(&p, g_Gh4);    bf16*  Gh   = (bf16*)p;
    cudaGetSymbolAddress(&p, g_Gl4);    bf16*  Gl   = (bf16*)p;
    cudaGetSymbolAddress(&p, g_HmT4);   float* HmT  = (float*)p;
    cudaGetSymbolAddress(&p, g_Hcat4);  half*  Hcat = (half*)p;
    cudaGetSymbolAddress(&p, g_Ccat4);  float* Ccat = (float*)p;
    cudaGetSymbolAddress(&p, g_meanT4); float* meanT= (float*)p;
    cudaGetSymbolAddress(&p, g_stdT4);  float* stdT = (float*)p;

    const size_t XN = 4ull * 4096 * 512;   // per-input XT elements
    const size_t WN = 512ull * 512;

    const int SM3 = 2 * 4 * 10240;   // 81920 (TERMS=3)
    const int SM1 = 2 * 2 * 10240;   // 40960 (TERMS=1)
    cudaFuncSetAttribute((gemm16<bf16,3,1,1>), cudaFuncAttributeMaxDynamicSharedMemorySize, SM3);
    cudaFuncSetAttribute((gemm16<bf16,3,0,1>), cudaFuncAttributeMaxDynamicSharedMemorySize, SM3);
    cudaFuncSetAttribute((gemm16<bf16,3,0,0>), cudaFuncAttributeMaxDynamicSharedMemorySize, SM3);
    cudaFuncSetAttribute((gemm16<half,1,0,0>), cudaFuncAttributeMaxDynamicSharedMemorySize, SM1);

    // 1) transpose+split inputs -> XT hi/lo bf16 [b][4096][512]
    transpose_split<<<dim3(128, 16, 4), dim3(32, 8)>>>(content_key, XTh + 0 * XN, XTl + 0 * XN);
    transpose_split<<<dim3(128, 16, 4), dim3(32, 8)>>>(style_key,   XTh + 1 * XN, XTl + 1 * XN);
    transpose_split<<<dim3(128, 16, 4), dim3(32, 8)>>>(style,       XTh + 2 * XN, XTl + 2 * XN);
    weight_split<<<dim3(3 * 262144 / 256), 256>>>(f_w, Wh + 0 * WN, Wl + 0 * WN, 262144);
    weight_split<<<dim3(1024), 256>>>(g_w, Wh + 1 * WN, Wl + 1 * WN, 262144);
    weight_split<<<dim3(1024), 256>>>(h_w, Wh + 2 * WN, Wl + 2 * WN, 262144);

    // 2) convs (bf16x3): F,G -> hi/lo bf16; H -> fp32
    gemm16<bf16,3,1,1><<<dim3(4, 32, 4), 256, SM3>>>(XTh + 0 * XN, XTl + 0 * XN,
        Wh + 0 * WN, Wl + 0 * WN, f_b, nullptr, Fh, Fl, 4096, 512, 512, 4096ull * 512, 0);
    gemm16<bf16,3,1,1><<<dim3(4, 32, 4), 256, SM3>>>(XTh + 1 * XN, XTl + 1 * XN,
        Wh + 1 * WN, Wl + 1 * WN, g_b, nullptr, Gh, Gl, 4096, 512, 512, 4096ull * 512, 0);
    gemm16<bf16,3,0,1><<<dim3(4, 32, 4), 256, SM3>>>(XTh + 2 * XN, XTl + 2 * XN,
        Wh + 2 * WN, Wl + 2 * WN, h_b, HmT, nullptr, nullptr, 4096, 512, 512, 4096ull * 512, 0);

    // 3) Hcat half [b][1024][4096] = [H[c][n] ; H^2]
    transpose_sq_half<<<dim3(16, 128, 4), dim3(32, 8)>>>(HmT, Hcat);

    // 4) attention logits (bf16x3, ~fp32 quality)
    gemm16<bf16,3,0,0><<<dim3(32, 32, 4), 256, SM3>>>(Fh, Fl, Gh, Gl, nullptr,
        attn, nullptr, nullptr, 4096, 4096, 512, 4096ull * 512, 4096ull * 512);

    // 5) triple-softmax mix -> S half
    softmax_mix_kernel<<<16384, 256>>>(attn, S, w_mix);

    // 6) mean/second GEMM (fp16): Ccat[n][1024] = S[n][m] * Hcat[cc][m]
    gemm16<half,1,0,0><<<dim3(8, 32, 4), 256, SM1>>>(S, nullptr, Hcat, nullptr, nullptr,
        Ccat, nullptr, nullptr, 4096, 1024, 4096, 4096ull * 4096, 1024ull * 4096);

    // 7) Ccat -> meanT/stdT [b][c][n]
    meanstd_transpose<<<dim3(16, 128, 4), dim3(32, 8)>>>(Ccat, meanT, stdT);

    // 8) finalize
    finalize_kernel<<<dim3(512, 4), 256>>>(content, meanT, stdT, out);
}

// round 6
// speedup vs baseline: 1.6590x; 1.1429x over previous
#include <cuda_runtime.h>
#include <cuda_bf16.h>
#include <cuda_fp16.h>
#include <math.h>
#include <stdint.h>

// ---------------- scratch (uint4 => 16B alignment for cp.async) ----------------
__device__ uint4 g_attn4 [16777216];   // fp32 attn  [4][4096][4096]
__device__ uint4 g_S4    [8388608];    // half  S    [4][4096][4096]
__device__ uint4 g_xth4  [3145728];    // bf16 XT hi, 3 inputs x [4][4096][512]
__device__ uint4 g_xtl4  [3145728];    // bf16 XT lo
__device__ uint4 g_wh4   [98304];      // bf16 W hi, 3 x [512][512]
__device__ uint4 g_wl4   [98304];
__device__ uint4 g_Fh4   [1048576];    // bf16 Fm hi [4][4096][512]
__device__ uint4 g_Fl4   [1048576];
__device__ uint4 g_Gh4   [1048576];
__device__ uint4 g_Gl4   [1048576];
__device__ uint4 g_HmT4  [2097152];    // fp32 Hm [4][4096][512] ([n][c])
__device__ uint4 g_Hcat4 [2097152];    // half Hcat [4][1024][4096]
__device__ uint4 g_Ccat4 [4194304];    // fp32 Ccat [4][4096][1024]
__device__ uint4 g_meanT4[2097152];    // fp32 [4][512][4096]
__device__ uint4 g_stdT4 [2097152];

// ---------------- helpers ----------------
__device__ __forceinline__ uint32_t smem_u32(const void* p) {
    uint32_t a;
    asm("{ .reg .u64 t; cvta.to.shared.u64 t, %1; cvt.u32.u64 %0, t; }" : "=r"(a) : "l"(p));
    return a;
}
__device__ __forceinline__ void cp16(uint32_t dst, const void* src) {
    asm volatile("cp.async.ca.shared.global [%0], [%1], 16;" :: "r"(dst), "l"(src));
}
__device__ __forceinline__ void ldsm4(uint32_t* r, uint32_t addr) {
    asm volatile("ldmatrix.sync.aligned.m8n8.x4.shared.b16 {%0,%1,%2,%3}, [%4];"
        : "=r"(r[0]), "=r"(r[1]), "=r"(r[2]), "=r"(r[3]) : "r"(addr));
}
__device__ __forceinline__ void mma16(float* d, const uint32_t* a, const uint32_t* b,
                                      const __nv_bfloat16*) {
    asm volatile("mma.sync.aligned.m16n8k16.row.col.f32.bf16.bf16.f32 "
        "{%0,%1,%2,%3}, {%4,%5,%6,%7}, {%8,%9}, {%0,%1,%2,%3};"
        : "+f"(d[0]), "+f"(d[1]), "+f"(d[2]), "+f"(d[3])
        : "r"(a[0]), "r"(a[1]), "r"(a[2]), "r"(a[3]), "r"(b[0]), "r"(b[1]));
}
__device__ __forceinline__ void mma16(float* d, const uint32_t* a, const uint32_t* b,
                                      const half*) {
    asm volatile("mma.sync.aligned.m16n8k16.row.col.f32.f16.f16.f32 "
        "{%0,%1,%2,%3}, {%4,%5,%6,%7}, {%8,%9}, {%0,%1,%2,%3};"
        : "+f"(d[0]), "+f"(d[1]), "+f"(d[2]), "+f"(d[3])
        : "r"(a[0]), "r"(a[1]), "r"(a[2]), "r"(a[3]), "r"(b[0]), "r"(b[1]));
}

// ---------------- GEMM: C[b][m][n] = sum_k A[m][k]*B[n][k] (+bias[n]) ----------------
// hi/lo 16-bit operands; TERMS=3: AhBh+AlBh+AhBl (error-compensated), TERMS=1: hi only.
// Block 128x128xKCH, 8 warps (2m x 4n), warp tile 64x32, cp.async double buffer,
// ldmatrix fragment loads. OUT_SPLIT=1: write bf16 hi/lo; else fp32.
template<typename T, int TERMS, int KCH, int OUT_SPLIT, int HAS_BIAS>
__global__ __launch_bounds__(256, 2) void gemm16(
    const T* __restrict__ Ah, const T* __restrict__ Al,
    const T* __restrict__ Bh, const T* __restrict__ Bl,
    const float* __restrict__ bias,
    float* __restrict__ Cf, T* __restrict__ Ch, T* __restrict__ Cl,
    int M, int N, int K, size_t sA, size_t sB)
{
    extern __shared__ char smem[];
    const int tid = threadIdx.x, lane = tid & 31, wid = tid >> 5;
    const int b = blockIdx.z;
    const int n0 = blockIdx.x * 128, m0 = blockIdx.y * 128;
    const T* Agh = Ah + (size_t)b * sA + (size_t)m0 * K;
    const T* Bgh = Bh + (size_t)b * sB + (size_t)n0 * K;
    const T* Agl = (TERMS == 3) ? (Al + (size_t)b * sA + (size_t)m0 * K) : nullptr;
    const T* Bgl = (TERMS == 3) ? (Bl + (size_t)b * sB + (size_t)n0 * K) : nullptr;

    const uint32_t sb = smem_u32(smem);
    constexpr uint32_t ST  = KCH * 2 + 16;            // row stride bytes (80 / 144)
    constexpr uint32_t TL  = 128u * ST;               // bytes per tile
    constexpr uint32_t BUF = (TERMS == 3 ? 4u : 2u) * TL;
    constexpr int LPR = KCH / 8;                      // lanes (16B chunks) per row
    constexpr int PP  = (128 * LPR) / 256;            // staging passes per tile

    const int wm = (wid >> 2) * 64, wn = (wid & 3) * 32;

    float acc[4][4][4];
    #pragma unroll
    for (int i = 0; i < 4; i++)
        #pragma unroll
        for (int j = 0; j < 4; j++)
            #pragma unroll
            for (int r = 0; r < 4; r++) acc[i][j][r] = 0.f;

    auto stage = [&](int ch, int buf) {
        uint32_t base = sb + buf * BUF;
        #pragma unroll
        for (int it = 0; it < PP; it++) {
            int idx = tid + it * 256;
            int r = idx / LPR, f = idx % LPR;
            uint32_t off = r * ST + f * 16;
            size_t go = (size_t)r * K + ch * KCH + f * 8;
            cp16(base + off, Agh + go);
            cp16(base + TL + off, Bgh + go);
            if (TERMS == 3) {
                cp16(base + 2 * TL + off, Agl + go);
                cp16(base + 3 * TL + off, Bgl + go);
            }
        }
        asm volatile("cp.async.commit_group;" ::: "memory");
    };

    // ldmatrix per-lane offsets
    const int t8 = lane >> 3, rr = lane & 7;
    const uint32_t a_off = (uint32_t)((t8 & 1) * 8 + rr) * ST + (t8 >> 1) * 16;
    const uint32_t b_off = (uint32_t)((t8 >> 1) * 8 + rr) * ST + (t8 & 1) * 16;

    const int NC = K / KCH;
    stage(0, 0);
    for (int ch = 0; ch < NC; ch++) {
        const int buf = ch & 1;
        if (ch + 1 < NC) {
            stage(ch + 1, buf ^ 1);
            asm volatile("cp.async.wait_group 1;" ::: "memory");
        } else {
            asm volatile("cp.async.wait_group 0;" ::: "memory");
        }
        __syncthreads();

        const uint32_t ab = sb + buf * BUF;   // A hi
        const uint32_t bb = ab + TL;          // B hi

        #pragma unroll
        for (int k16 = 0; k16 < KCH / 16; k16++) {
            const uint32_t kb = k16 * 32;
            // B fragments: 4 n8-tiles via 2x ldmatrix.x4 (hi), 2x (lo)
            uint32_t bhf[4][2], blf[4][2];
            #pragma unroll
            for (int pr = 0; pr < 2; pr++) {
                uint32_t r4[4];
                ldsm4(r4, bb + (uint32_t)(wn + pr * 16) * ST + b_off + kb);
                bhf[pr * 2][0] = r4[0]; bhf[pr * 2][1] = r4[1];
                bhf[pr * 2 + 1][0] = r4[2]; bhf[pr * 2 + 1][1] = r4[3];
                if (TERMS == 3) {
                    ldsm4(r4, bb + 2 * TL + (uint32_t)(wn + pr * 16) * ST + b_off + kb);
                    blf[pr * 2][0] = r4[0]; blf[pr * 2][1] = r4[1];
                    blf[pr * 2 + 1][0] = r4[2]; blf[pr * 2 + 1][1] = r4[3];
                }
            }
            #pragma unroll
            for (int im = 0; im < 4; im++) {
                uint32_t af[4];
                ldsm4(af, ab + (uint32_t)(wm + im * 16) * ST + a_off + kb);
                #pragma unroll
                for (int jn = 0; jn < 4; jn++) {
                    mma16(acc[im][jn], af, bhf[jn], (const T*)nullptr);
                    if (TERMS == 3) mma16(acc[im][jn], af, blf[jn], (const T*)nullptr);
                }
                if (TERMS == 3) {
                    uint32_t alf[4];
                    ldsm4(alf, ab + 2 * TL + (uint32_t)(wm + im * 16) * ST + a_off + kb);
                    #pragma unroll
                    for (int jn = 0; jn < 4; jn++)
                        mma16(acc[im][jn], alf, bhf[jn], (const T*)nullptr);
                }
            }
        }
        __syncthreads();
    }

    // epilogue
    #pragma unroll
    for (int im = 0; im < 4; im++) {
        int r = m0 + wm + im * 16 + (lane >> 2);
        #pragma unroll
        for (int jn = 0; jn < 4; jn++) {
            int cc = n0 + wn + jn * 8 + (lane & 3) * 2;
            float b0 = 0.f, b1 = 0.f;
            if (HAS_BIAS) { b0 = __ldg(&bias[cc]); b1 = __ldg(&bias[cc + 1]); }
            float v00 = acc[im][jn][0] + b0, v01 = acc[im][jn][1] + b1;
            float v10 = acc[im][jn][2] + b0, v11 = acc[im][jn][3] + b1;
            size_t o0 = (size_t)b * (size_t)M * N + (size_t)r * N + cc;
            size_t o1 = o0 + (size_t)8 * N;
            if constexpr (OUT_SPLIT) {
                __nv_bfloat16 h00 = __float2bfloat16_rn(v00), h01 = __float2bfloat16_rn(v01);
                __nv_bfloat16 h10 = __float2bfloat16_rn(v10), h11 = __float2bfloat16_rn(v11);
                *(__nv_bfloat162*)((__nv_bfloat16*)Ch + o0) = __nv_bfloat162(h00, h01);
                *(__nv_bfloat162*)((__nv_bfloat16*)Ch + o1) = __nv_bfloat162(h10, h11);
                *(__nv_bfloat162*)((__nv_bfloat16*)Cl + o0) = __nv_bfloat162(
                    __float2bfloat16_rn(v00 - __bfloat162float(h00)),
                    __float2bfloat16_rn(v01 - __bfloat162float(h01)));
                *(__nv_bfloat162*)((__nv_bfloat16*)Cl + o1) = __nv_bfloat162(
                    __float2bfloat16_rn(v10 - __bfloat162float(h10)),
                    __float2bfloat16_rn(v11 - __bfloat162float(h11)));
            } else {
                *(float2*)(Cf + o0) = make_float2(v00, v01);
                *(float2*)(Cf + o1) = make_float2(v10, v11);
            }
        }
    }
}

// ---------------- transpose+split: fp32 [b][512][4096] -> hi/lo bf16 [b][4096][512] ----------------
__global__ void transpose_split(const float* __restrict__ src,
                                __nv_bfloat16* __restrict__ dh, __nv_bfloat16* __restrict__ dl)
{
    __shared__ float t[32][33];
    int b = blockIdx.z;
    const float* s = src + (size_t)b * 512ull * 4096ull;
    size_t dbo = (size_t)b * 512ull * 4096ull;
    int c0 = blockIdx.x * 32, r0 = blockIdx.y * 32;
    int tx = threadIdx.x, ty = threadIdx.y;
    #pragma unroll
    for (int k = 0; k < 4; k++)
        t[ty + k * 8][tx] = s[(size_t)(r0 + ty + k * 8) * 4096 + c0 + tx];
    __syncthreads();
    #pragma unroll
    for (int k = 0; k < 4; k++) {
        float v = t[tx][ty + k * 8];
        size_t o = dbo + (size_t)(c0 + ty + k * 8) * 512 + r0 + tx;
        __nv_bfloat16 h = __float2bfloat16_rn(v);
        dh[o] = h;
        dl[o] = __float2bfloat16_rn(v - __bfloat162float(h));
    }
}

__global__ void weight_split(const float* __restrict__ w,
                             __nv_bfloat16* __restrict__ wh, __nv_bfloat16* __restrict__ wl, int n)
{
    int i = blockIdx.x * 256 + threadIdx.x;
    if (i < n) {
        float v = w[i];
        __nv_bfloat16 h = __float2bfloat16_rn(v);
        wh[i] = h;
        wl[i] = __float2bfloat16_rn(v - __bfloat162float(h));
    }
}

// HmT fp32 [b][4096(n)][512(c)] -> Hcat half [b][1024][4096]: [H ; H^2]
__global__ void transpose_sq_half(const float* __restrict__ src, half* __restrict__ dst)
{
    __shared__ float t[32][33];
    int b = blockIdx.z;
    const float* s = src + (size_t)b * 4096ull * 512ull;
    half* d = dst + (size_t)b * 1024ull * 4096ull;
    int c0 = blockIdx.x * 32, n0 = blockIdx.y * 32;
    int tx = threadIdx.x, ty = threadIdx.y;
    #pragma unroll
    for (int k = 0; k < 4; k++)
        t[ty + k * 8][tx] = s[(size_t)(n0 + ty + k * 8) * 512 + c0 + tx];
    __syncthreads();
    #pragma unroll
    for (int k = 0; k < 4; k++) {
        float v = t[tx][ty + k * 8];
        d[(size_t)(c0 + ty + k * 8) * 4096 + n0 + tx] = __float2half_rn(v);
        d[(size_t)(512 + c0 + ty + k * 8) * 4096 + n0 + tx] = __float2half_rn(v * v);
    }
}

// Ccat [b][n][1024] -> meanT/stdT [b][c][n]
__global__ void meanstd_transpose(const float* __restrict__ Ccat,
                                  float* __restrict__ meanT, float* __restrict__ stdT)
{
    __shared__ float tm[32][33], ts[32][33];
    int b = blockIdx.z;
    int c0 = blockIdx.x * 32, n0 = blockIdx.y * 32;
    const float* Cb = Ccat + (size_t)b * 4096ull * 1024ull;
    int tx = threadIdx.x, ty = threadIdx.y;
    #pragma unroll
    for (int k = 0; k < 4; k++) {
        int n = n0 + ty + k * 8;
        float mn = Cb[(size_t)n * 1024 + c0 + tx];
        float sc = Cb[(size_t)n * 1024 + 512 + c0 + tx];
        tm[ty + k * 8][tx] = mn;
        ts[ty + k * 8][tx] = sqrtf(fmaxf(sc - mn * mn, 0.f));
    }
    __syncthreads();
    size_t ob = (size_t)b * 512ull * 4096ull;
    #pragma unroll
    for (int k = 0; k < 4; k++) {
        int c = c0 + ty + k * 8;
        meanT[ob + (size_t)c * 4096 + n0 + tx] = tm[tx][ty + k * 8];
        stdT [ob + (size_t)c * 4096 + n0 + tx] = ts[tx][ty + k * 8];
    }
}

// ---------------- block reductions ----------------
__device__ __forceinline__ float block_reduce_max(float v, float* red) {
    #pragma unroll
    for (int o = 16; o > 0; o >>= 1) v = fmaxf(v, __shfl_xor_sync(0xffffffffu, v, o));
    int wid = threadIdx.x >> 5, lid = threadIdx.x & 31;
    if (lid == 0) red[wid] = v;
    __syncthreads();
    if (wid == 0) {
        v = (lid < 8) ? red[lid] : -1e30f;
        #pragma unroll
        for (int o = 4; o > 0; o >>= 1) v = fmaxf(v, __shfl_xor_sync(0xffffffffu, v, o));
        if (lid == 0) red[0] = v;
    }
    __syncthreads();
    float r = red[0];
    __syncthreads();
    return r;
}
__device__ __forceinline__ float block_reduce_sum(float v, float* red) {
    #pragma unroll
    for (int o = 16; o > 0; o >>= 1) v += __shfl_xor_sync(0xffffffffu, v, o);
    int wid = threadIdx.x >> 5, lid = threadIdx.x & 31;
    if (lid == 0) red[wid] = v;
    __syncthreads();
    if (wid == 0) {
        v = (lid < 8) ? red[lid] : 0.f;
        #pragma unroll
        for (int o = 4; o > 0; o >>= 1) v += __shfl_xor_sync(0xffffffffu, v, o);
        if (lid == 0) red[0] = v;
    }
    __syncthreads();
    float r = red[0];
    __syncthreads();
    return r;
}

// ---------------- softmax mix: fp32 in -> half S out ----------------
// e2 = exp(max(v,0)-m2) with m2=max(m1,0) satisfies: e2 = (v>0) ? e1 : exp(-m2).
__global__ __launch_bounds__(256) void softmax_mix_kernel(
    const float* __restrict__ attn, half* __restrict__ S, const float* __restrict__ w_mix)
{
    __shared__ float e1s[4096];
    __shared__ float red[32];
    const float* p = attn + (size_t)blockIdx.x * 4096;
    half* q = S + (size_t)blockIdx.x * 4096;
    int tid = threadIdx.x;

    float lmax = -1e30f;
    for (int i = tid; i < 4096; i += 256) {
        float v = p[i];
        e1s[i] = v;
        lmax = fmaxf(lmax, v);
    }
    float m1 = block_reduce_max(lmax, red);
    float m2 = fmaxf(m1, 0.f);
    float Cneg = __expf(-m2);

    float z1 = 0.f, z2p = 0.f, nneg = 0.f;
    for (int i = tid; i < 4096; i += 256) {
        float v = e1s[i];
        float e1 = __expf(v - m1);
        bool pos = v > 0.f;
        z1 += e1;
        if (pos) z2p += e1; else nneg += 1.f;
        e1s[i] = pos ? e1 : -e1;     // sign encodes (v>0)
    }
    float Z1 = block_reduce_sum(z1, red);
    float Z2 = block_reduce_sum(z2p, red) + block_reduce_sum(nneg, red) * Cneg;

    float ew0 = __expf(w_mix[0]), ew1 = __expf(w_mix[1]);
    float inv = 1.f / (ew0 + ew1);
    float iz1 = (ew0 * inv) / Z1;
    float iz2 = (ew1 * inv) / Z2;
    float Cn2 = Cneg * iz2;

    float za = 0.f;
    for (int i = tid; i < 4096; i += 256) {
        float se = e1s[i];
        float e1 = fabsf(se);
        float A = (se > 0.f) ? e1 * (iz1 + iz2) : (e1 * iz1 + Cn2);
        float e = __expf(A);   // A in (0,1]
        e1s[i] = e;
        za += e;
    }
    float ZA = block_reduce_sum(za, red);
    float izA = 1.f / ZA;
    for (int i = tid; i < 4096; i += 256)
        q[i] = __float2half_rn(e1s[i] * izA);
}

// ---------------- finalize: out = stdT * mvn(content) + meanT ----------------
__global__ __launch_bounds__(256) void finalize_kernel(
    const float* __restrict__ content, const float* __restrict__ meanT,
    const float* __restrict__ stdT, float* __restrict__ out)
{
    __shared__ float red[32];
    int c = blockIdx.x, b = blockIdx.y;
    size_t off = ((size_t)b * 512 + c) * 4096;
    const float* x = content + off;
    int tid = threadIdx.x;

    float s = 0.f, ss = 0.f;
    for (int i = tid; i < 4096; i += 256) {
        float v = x[i];
        s += v; ss += v * v;
    }
    s = block_reduce_sum(s, red);
    ss = block_reduce_sum(ss, red);
    float mu = s * (1.f / 4096.f);
    float var = (ss - 4096.f * mu * mu) * (1.f / 4095.f);
    float rstd = rsqrtf(var + 1e-5f);

    for (int i = tid; i < 4096; i += 256)
        out[off + i] = stdT[off + i] * ((x[i] - mu) * rstd) + meanT[off + i];
}

// ---------------- launch ----------------
extern "C" void kernel_launch(void* const* d_in, const int* in_sizes, int n_in,
                              void* d_out, int out_size)
{
    const float* content     = (const float*)d_in[0];
    const float* style       = (const float*)d_in[1];
    const float* content_key = (const float*)d_in[2];
    const float* style_key   = (const float*)d_in[3];
    const float* f_w = (const float*)d_in[4];
    const float* f_b = (const float*)d_in[5];
    const float* g_w = (const float*)d_in[6];
    const float* g_b = (const float*)d_in[7];
    const float* h_w = (const float*)d_in[8];
    const float* h_b = (const float*)d_in[9];
    const float* w_mix = (const float*)d_in[10];
    float* out = (float*)d_out;

    typedef __nv_bfloat16 bf16;
    void *p;
    cudaGetSymbolAddress(&p, g_attn4);  float* attn = (float*)p;
    cudaGetSymbolAddress(&p, g_S4);     half*  S    = (half*)p;
    cudaGetSymbolAddress(&p, g_xth4);   bf16*  XTh  = (bf16*)p;
    cudaGetSymbolAddress(&p, g_xtl4);   bf16*  XTl  = (bf16*)p;
    cudaGetSymbolAddress(&p, g_wh4);    bf16*  Wh   = (bf16*)p;
    cudaGetSymbolAddress(&p, g_wl4);    bf16*  Wl   = (bf16*)p;
    cudaGetSymbolAddress(&p, g_Fh4);    bf16*  Fh   = (bf16*)p;
    cudaGetSymbolAddress(&p, g_Fl4);    bf16*  Fl   = (bf16*)p;
    cudaGetSymbolAddress(&p, g_Gh4);    bf16*  Gh   = (bf16*)p;
    cudaGetSymbolAddress(&p, g_Gl4);    bf16*  Gl   = (bf16*)p;
    cudaGetSymbolAddress(&p, g_HmT4);   float* HmT  = (float*)p;
    cudaGetSymbolAddress(&p, g_Hcat4);  half*  Hcat = (half*)p;
    cudaGetSymbolAddress(&p, g_Ccat4);  float* Ccat = (float*)p;
    cudaGetSymbolAddress(&p, g_meanT4); float* meanT= (float*)p;
    cudaGetSymbolAddress(&p, g_stdT4);  float* stdT = (float*)p;

    const size_t XN = 4ull * 4096 * 512;
    const size_t WN = 512ull * 512;

    const int SM3 = 2 * 4 * (128 * 80);    // 81920  (TERMS=3, KCH=32)
    const int SM1 = 2 * 2 * (128 * 144);   // 73728  (TERMS=1, KCH=64)
    cudaFuncSetAttribute((gemm16<bf16,3,32,1,1>), cudaFuncAttributeMaxDynamicSharedMemorySize, SM3);
    cudaFuncSetAttribute((gemm16<bf16,3,32,0,1>), cudaFuncAttributeMaxDynamicSharedMemorySize, SM3);
    cudaFuncSetAttribute((gemm16<bf16,3,32,0,0>), cudaFuncAttributeMaxDynamicSharedMemorySize, SM3);
    cudaFuncSetAttribute((gemm16<half,1,64,0,0>), cudaFuncAttributeMaxDynamicSharedMemorySize, SM1);

    // 1) transpose+split inputs -> XT hi/lo bf16 [b][4096][512]
    transpose_split<<<dim3(128, 16, 4), dim3(32, 8)>>>(content_key, XTh + 0 * XN, XTl + 0 * XN);
    transpose_split<<<dim3(128, 16, 4), dim3(32, 8)>>>(style_key,   XTh + 1 * XN, XTl + 1 * XN);
    transpose_split<<<dim3(128, 16, 4), dim3(32, 8)>>>(style,       XTh + 2 * XN, XTl + 2 * XN);
    weight_split<<<dim3(1024), 256>>>(f_w, Wh + 0 * WN, Wl + 0 * WN, 262144);
    weight_split<<<dim3(1024), 256>>>(g_w, Wh + 1 * WN, Wl + 1 * WN, 262144);
    weight_split<<<dim3(1024), 256>>>(h_w, Wh + 2 * WN, Wl + 2 * WN, 262144);

    // 2) convs (bf16x3): F,G -> hi/lo bf16; H -> fp32
    gemm16<bf16,3,32,1,1><<<dim3(4, 32, 4), 256, SM3>>>(XTh + 0 * XN, XTl + 0 * XN,
        Wh + 0 * WN, Wl + 0 * WN, f_b, nullptr, Fh, Fl, 4096, 512, 512, 4096ull * 512, 0);
    gemm16<bf16,3,32,1,1><<<dim3(4, 32, 4), 256, SM3>>>(XTh + 1 * XN, XTl + 1 * XN,
        Wh + 1 * WN, Wl + 1 * WN, g_b, nullptr, Gh, Gl, 4096, 512, 512, 4096ull * 512, 0);
    gemm16<bf16,3,32,0,1><<<dim3(4, 32, 4), 256, SM3>>>(XTh + 2 * XN, XTl + 2 * XN,
        Wh + 2 * WN, Wl + 2 * WN, h_b, HmT, nullptr, nullptr, 4096, 512, 512, 4096ull * 512, 0);

    // 3) Hcat half [b][1024][4096] = [H[c][n] ; H^2]
    transpose_sq_half<<<dim3(16, 128, 4), dim3(32, 8)>>>(HmT, Hcat);

    // 4) attention logits (bf16x3, ~fp32 quality)
    gemm16<bf16,3,32,0,0><<<dim3(32, 32, 4), 256, SM3>>>(Fh, Fl, Gh, Gl, nullptr,
        attn, nullptr, nullptr, 4096, 4096, 512, 4096ull * 512, 4096ull * 512);

    // 5) triple-softmax mix -> S half
    softmax_mix_kernel<<<16384, 256>>>(attn, S, w_mix);

    // 6) mean/second GEMM (fp16, KCH=64): Ccat[n][1024] = S[n][m] * Hcat[cc][m]
    gemm16<half,1,64,0,0><<<dim3(8, 32, 4), 256, SM1>>>(S, nullptr, Hcat, nullptr, nullptr,
        Ccat, nullptr, nullptr, 4096, 1024, 4096, 4096ull * 4096, 1024ull * 4096);

    // 7) Ccat -> meanT/stdT [b][c][n]
    meanstd_transpose<<<dim3(16, 128, 4), dim3(32, 8)>>>(Ccat, meanT, stdT);

    // 8) finalize
    finalize_kernel<<<dim3(512, 4), 256>>>(content, meanT, stdT, out);
}

// round 7
// speedup vs baseline: 1.6690x; 1.0060x over previous
#include <cuda_runtime.h>
#include <cuda_bf16.h>
#include <cuda_fp16.h>
#include <math.h>
#include <stdint.h>

// ---------------- scratch (uint4 => 16B alignment for cp.async) ----------------
__device__ uint4 g_attn4 [16777216];   // fp32 attn  [4][4096][4096]
__device__ uint4 g_S4    [8388608];    // half  S    [4][4096][4096]
__device__ uint4 g_xth4  [3145728];    // bf16 XT hi, 3 inputs x [4][4096][512]
__device__ uint4 g_xtl4  [3145728];    // bf16 XT lo
__device__ uint4 g_wh4   [98304];      // bf16 W hi, 3 x [512][512]
__device__ uint4 g_wl4   [98304];
__device__ uint4 g_Fh4   [1048576];    // bf16 Fm hi [4][4096][512]
__device__ uint4 g_Fl4   [1048576];
__device__ uint4 g_Gh4   [1048576];
__device__ uint4 g_Gl4   [1048576];
__device__ uint4 g_HmT4  [2097152];    // fp32 Hm [4][4096][512] ([n][c])
__device__ uint4 g_Hcat4 [2097152];    // half Hcat [4][1024][4096]
__device__ uint4 g_Ccat4 [4194304];    // fp32 Ccat [4][4096][1024]
__device__ uint4 g_meanT4[2097152];    // fp32 [4][512][4096]
__device__ uint4 g_stdT4 [2097152];

// ---------------- helpers ----------------
__device__ __forceinline__ uint32_t smem_u32(const void* p) {
    uint32_t a;
    asm("{ .reg .u64 t; cvta.to.shared.u64 t, %1; cvt.u32.u64 %0, t; }" : "=r"(a) : "l"(p));
    return a;
}
__device__ __forceinline__ void cp16(uint32_t dst, const void* src) {
    asm volatile("cp.async.ca.shared.global [%0], [%1], 16;" :: "r"(dst), "l"(src));
}
__device__ __forceinline__ void ldsm4(uint32_t* r, uint32_t addr) {
    asm volatile("ldmatrix.sync.aligned.m8n8.x4.shared.b16 {%0,%1,%2,%3}, [%4];"
        : "=r"(r[0]), "=r"(r[1]), "=r"(r[2]), "=r"(r[3]) : "r"(addr));
}
__device__ __forceinline__ void mma16(float* d, const uint32_t* a, const uint32_t* b,
                                      const __nv_bfloat16*) {
    asm volatile("mma.sync.aligned.m16n8k16.row.col.f32.bf16.bf16.f32 "
        "{%0,%1,%2,%3}, {%4,%5,%6,%7}, {%8,%9}, {%0,%1,%2,%3};"
        : "+f"(d[0]), "+f"(d[1]), "+f"(d[2]), "+f"(d[3])
        : "r"(a[0]), "r"(a[1]), "r"(a[2]), "r"(a[3]), "r"(b[0]), "r"(b[1]));
}
__device__ __forceinline__ void mma16(float* d, const uint32_t* a, const uint32_t* b,
                                      const half*) {
    asm volatile("mma.sync.aligned.m16n8k16.row.col.f32.f16.f16.f32 "
        "{%0,%1,%2,%3}, {%4,%5,%6,%7}, {%8,%9}, {%0,%1,%2,%3};"
        : "+f"(d[0]), "+f"(d[1]), "+f"(d[2]), "+f"(d[3])
        : "r"(a[0]), "r"(a[1]), "r"(a[2]), "r"(a[3]), "r"(b[0]), "r"(b[1]));
}

// FMA-only exp: MUFU rt=8/SMSP on B300 makes __expf ~15x slower than this.
// Schraudolph round-to-int via magic add, deg-6 Taylor of 2^f on [-0.5,0.5],
// exponent via integer add on float bits. rel err ~1.5e-7. Valid for x in
// [-80, 80]; inputs here are <= ~1.
__device__ __forceinline__ float fast_exp(float x) {
    x = fmaxf(x, -80.f);
    float t = x * 1.44269504088896f;          // log2(e)
    float z = t + 12582912.f;                 // 1.5 * 2^23: round-to-nearest
    int   i = __float_as_int(z) - 0x4B400000; // integer part
    float f = t - (z - 12582912.f);           // f in [-0.5, 0.5]
    // 2^f Taylor: ln2^k / k!
    float p = 1.53989037e-4f;
    p = fmaf(p, f, 1.33335581e-3f);
    p = fmaf(p, f, 9.61812910e-3f);
    p = fmaf(p, f, 5.55041087e-2f);
    p = fmaf(p, f, 2.40226507e-1f);
    p = fmaf(p, f, 6.93147181e-1f);
    p = fmaf(p, f, 1.0f);
    return __int_as_float(__float_as_int(p) + (i << 23));
}

// FMA-only sqrt via bit-hack rsqrt + 2 Newton iters; x>=0, returns sqrt(x).
__device__ __forceinline__ float fast_sqrt(float v) {
    float x = fmaxf(v, 1e-30f);
    float xh = 0.5f * x;
    float y = __int_as_float(0x5f375a86 - (__float_as_int(x) >> 1));
    y = y * fmaf(-xh, y * y, 1.5f);
    y = y * fmaf(-xh, y * y, 1.5f);
    return v * y;   // v=0 -> 0
}

// ---------------- GEMM: C[b][m][n] = sum_k A[m][k]*B[n][k] (+bias[n]) ----------------
// hi/lo 16-bit operands; TERMS=3: AhBh+AlBh+AhBl (error-compensated), TERMS=1: hi only.
// Block 128x128xKCH, 8 warps (2m x 4n), warp tile 64x32, cp.async double buffer,
// ldmatrix fragment loads. OUT_SPLIT=1: write bf16 hi/lo; else fp32.
template<typename T, int TERMS, int KCH, int OUT_SPLIT, int HAS_BIAS>
__global__ __launch_bounds__(256, 2) void gemm16(
    const T* __restrict__ Ah, const T* __restrict__ Al,
    const T* __restrict__ Bh, const T* __restrict__ Bl,
    const float* __restrict__ bias,
    float* __restrict__ Cf, T* __restrict__ Ch, T* __restrict__ Cl,
    int M, int N, int K, size_t sA, size_t sB)
{
    extern __shared__ char smem[];
    const int tid = threadIdx.x, lane = tid & 31, wid = tid >> 5;
    const int b = blockIdx.z;
    const int n0 = blockIdx.x * 128, m0 = blockIdx.y * 128;
    const T* Agh = Ah + (size_t)b * sA + (size_t)m0 * K;
    const T* Bgh = Bh + (size_t)b * sB + (size_t)n0 * K;
    const T* Agl = (TERMS == 3) ? (Al + (size_t)b * sA + (size_t)m0 * K) : nullptr;
    const T* Bgl = (TERMS == 3) ? (Bl + (size_t)b * sB + (size_t)n0 * K) : nullptr;

    const uint32_t sb = smem_u32(smem);
    constexpr uint32_t ST  = KCH * 2 + 16;            // row stride bytes (80 / 144)
    constexpr uint32_t TL  = 128u * ST;               // bytes per tile
    constexpr uint32_t BUF = (TERMS == 3 ? 4u : 2u) * TL;
    constexpr int LPR = KCH / 8;                      // lanes (16B chunks) per row
    constexpr int PP  = (128 * LPR) / 256;            // staging passes per tile

    const int wm = (wid >> 2) * 64, wn = (wid & 3) * 32;

    float acc[4][4][4];
    #pragma unroll
    for (int i = 0; i < 4; i++)
        #pragma unroll
        for (int j = 0; j < 4; j++)
            #pragma unroll
            for (int r = 0; r < 4; r++) acc[i][j][r] = 0.f;

    auto stage = [&](int ch, int buf) {
        uint32_t base = sb + buf * BUF;
        #pragma unroll
        for (int it = 0; it < PP; it++) {
            int idx = tid + it * 256;
            int r = idx / LPR, f = idx % LPR;
            uint32_t off = r * ST + f * 16;
            size_t go = (size_t)r * K + ch * KCH + f * 8;
            cp16(base + off, Agh + go);
            cp16(base + TL + off, Bgh + go);
            if (TERMS == 3) {
                cp16(base + 2 * TL + off, Agl + go);
                cp16(base + 3 * TL + off, Bgl + go);
            }
        }
        asm volatile("cp.async.commit_group;" ::: "memory");
    };

    // ldmatrix per-lane offsets
    const int t8 = lane >> 3, rr = lane & 7;
    const uint32_t a_off = (uint32_t)((t8 & 1) * 8 + rr) * ST + (t8 >> 1) * 16;
    const uint32_t b_off = (uint32_t)((t8 >> 1) * 8 + rr) * ST + (t8 & 1) * 16;

    const int NC = K / KCH;
    stage(0, 0);
    for (int ch = 0; ch < NC; ch++) {
        const int buf = ch & 1;
        if (ch + 1 < NC) {
            stage(ch + 1, buf ^ 1);
            asm volatile("cp.async.wait_group 1;" ::: "memory");
        } else {
            asm volatile("cp.async.wait_group 0;" ::: "memory");
        }
        __syncthreads();

        const uint32_t ab = sb + buf * BUF;   // A hi
        const uint32_t bb = ab + TL;          // B hi

        #pragma unroll
        for (int k16 = 0; k16 < KCH / 16; k16++) {
            const uint32_t kb = k16 * 32;
            // B fragments: 4 n8-tiles via 2x ldmatrix.x4 (hi), 2x (lo)
            uint32_t bhf[4][2], blf[4][2];
            #pragma unroll
            for (int pr = 0; pr < 2; pr++) {
                uint32_t r4[4];
                ldsm4(r4, bb + (uint32_t)(wn + pr * 16) * ST + b_off + kb);
                bhf[pr * 2][0] = r4[0]; bhf[pr * 2][1] = r4[1];
                bhf[pr * 2 + 1][0] = r4[2]; bhf[pr * 2 + 1][1] = r4[3];
                if (TERMS == 3) {
                    ldsm4(r4, bb + 2 * TL + (uint32_t)(wn + pr * 16) * ST + b_off + kb);
                    blf[pr * 2][0] = r4[0]; blf[pr * 2][1] = r4[1];
                    blf[pr * 2 + 1][0] = r4[2]; blf[pr * 2 + 1][1] = r4[3];
                }
            }
            #pragma unroll
            for (int im = 0; im < 4; im++) {
                uint32_t af[4];
                ldsm4(af, ab + (uint32_t)(wm + im * 16) * ST + a_off + kb);
                #pragma unroll
                for (int jn = 0; jn < 4; jn++) {
                    mma16(acc[im][jn], af, bhf[jn], (const T*)nullptr);
                    if (TERMS == 3) mma16(acc[im][jn], af, blf[jn], (const T*)nullptr);
                }
                if (TERMS == 3) {
                    uint32_t alf[4];
                    ldsm4(alf, ab + 2 * TL + (uint32_t)(wm + im * 16) * ST + a_off + kb);
                    #pragma unroll
                    for (int jn = 0; jn < 4; jn++)
                        mma16(acc[im][jn], alf, bhf[jn], (const T*)nullptr);
                }
            }
        }
        __syncthreads();
    }

    // epilogue
    #pragma unroll
    for (int im = 0; im < 4; im++) {
        int r = m0 + wm + im * 16 + (lane >> 2);
        #pragma unroll
        for (int jn = 0; jn < 4; jn++) {
            int cc = n0 + wn + jn * 8 + (lane & 3) * 2;
            float b0 = 0.f, b1 = 0.f;
            if (HAS_BIAS) { b0 = __ldg(&bias[cc]); b1 = __ldg(&bias[cc + 1]); }
            float v00 = acc[im][jn][0] + b0, v01 = acc[im][jn][1] + b1;
            float v10 = acc[im][jn][2] + b0, v11 = acc[im][jn][3] + b1;
            size_t o0 = (size_t)b * (size_t)M * N + (size_t)r * N + cc;
            size_t o1 = o0 + (size_t)8 * N;
            if constexpr (OUT_SPLIT) {
                __nv_bfloat16 h00 = __float2bfloat16_rn(v00), h01 = __float2bfloat16_rn(v01);
                __nv_bfloat16 h10 = __float2bfloat16_rn(v10), h11 = __float2bfloat16_rn(v11);
                *(__nv_bfloat162*)((__nv_bfloat16*)Ch + o0) = __nv_bfloat162(h00, h01);
                *(__nv_bfloat162*)((__nv_bfloat16*)Ch + o1) = __nv_bfloat162(h10, h11);
                *(__nv_bfloat162*)((__nv_bfloat16*)Cl + o0) = __nv_bfloat162(
                    __float2bfloat16_rn(v00 - __bfloat162float(h00)),
                    __float2bfloat16_rn(v01 - __bfloat162float(h01)));
                *(__nv_bfloat162*)((__nv_bfloat16*)Cl + o1) = __nv_bfloat162(
                    __float2bfloat16_rn(v10 - __bfloat162float(h10)),
                    __float2bfloat16_rn(v11 - __bfloat162float(h11)));
            } else {
                *(float2*)(Cf + o0) = make_float2(v00, v01);
                *(float2*)(Cf + o1) = make_float2(v10, v11);
            }
        }
    }
}

// ---------------- transpose+split: fp32 [b][512][4096] -> hi/lo bf16 [b][4096][512] ----------------
__global__ void transpose_split(const float* __restrict__ src,
                                __nv_bfloat16* __restrict__ dh, __nv_bfloat16* __restrict__ dl)
{
    __shared__ float t[32][33];
    int b = blockIdx.z;
    const float* s = src + (size_t)b * 512ull * 4096ull;
    size_t dbo = (size_t)b * 512ull * 4096ull;
    int c0 = blockIdx.x * 32, r0 = blockIdx.y * 32;
    int tx = threadIdx.x, ty = threadIdx.y;
    #pragma unroll
    for (int k = 0; k < 4; k++)
        t[ty + k * 8][tx] = s[(size_t)(r0 + ty + k * 8) * 4096 + c0 + tx];
    __syncthreads();
    #pragma unroll
    for (int k = 0; k < 4; k++) {
        float v = t[tx][ty + k * 8];
        size_t o = dbo + (size_t)(c0 + ty + k * 8) * 512 + r0 + tx;
        __nv_bfloat16 h = __float2bfloat16_rn(v);
        dh[o] = h;
        dl[o] = __float2bfloat16_rn(v - __bfloat162float(h));
    }
}

__global__ void weight_split(const float* __restrict__ w,
                             __nv_bfloat16* __restrict__ wh, __nv_bfloat16* __restrict__ wl, int n)
{
    int i = blockIdx.x * 256 + threadIdx.x;
    if (i < n) {
        float v = w[i];
        __nv_bfloat16 h = __float2bfloat16_rn(v);
        wh[i] = h;
        wl[i] = __float2bfloat16_rn(v - __bfloat162float(h));
    }
}

// HmT fp32 [b][4096(n)][512(c)] -> Hcat half [b][1024][4096]: [H ; H^2]
__global__ void transpose_sq_half(const float* __restrict__ src, half* __restrict__ dst)
{
    __shared__ float t[32][33];
    int b = blockIdx.z;
    const float* s = src + (size_t)b * 4096ull * 512ull;
    half* d = dst + (size_t)b * 1024ull * 4096ull;
    int c0 = blockIdx.x * 32, n0 = blockIdx.y * 32;
    int tx = threadIdx.x, ty = threadIdx.y;
    #pragma unroll
    for (int k = 0; k < 4; k++)
        t[ty + k * 8][tx] = s[(size_t)(n0 + ty + k * 8) * 512 + c0 + tx];
    __syncthreads();
    #pragma unroll
    for (int k = 0; k < 4; k++) {
        float v = t[tx][ty + k * 8];
        d[(size_t)(c0 + ty + k * 8) * 4096 + n0 + tx] = __float2half_rn(v);
        d[(size_t)(512 + c0 + ty + k * 8) * 4096 + n0 + tx] = __float2half_rn(v * v);
    }
}

// Ccat [b][n][1024] -> meanT/stdT [b][c][n]   (FMA-only sqrt)
__global__ void meanstd_transpose(const float* __restrict__ Ccat,
                                  float* __restrict__ meanT, float* __restrict__ stdT)
{
    __shared__ float tm[32][33], ts[32][33];
    int b = blockIdx.z;
    int c0 = blockIdx.x * 32, n0 = blockIdx.y * 32;
    const float* Cb = Ccat + (size_t)b * 4096ull * 1024ull;
    int tx = threadIdx.x, ty = threadIdx.y;
    #pragma unroll
    for (int k = 0; k < 4; k++) {
        int n = n0 + ty + k * 8;
        float mn = Cb[(size_t)n * 1024 + c0 + tx];
        float sc = Cb[(size_t)n * 1024 + 512 + c0 + tx];
        tm[ty + k * 8][tx] = mn;
        ts[ty + k * 8][tx] = fast_sqrt(fmaxf(sc - mn * mn, 0.f));
    }
    __syncthreads();
    size_t ob = (size_t)b * 512ull * 4096ull;
    #pragma unroll
    for (int k = 0; k < 4; k++) {
        int c = c0 + ty + k * 8;
        meanT[ob + (size_t)c * 4096 + n0 + tx] = tm[tx][ty + k * 8];
        stdT [ob + (size_t)c * 4096 + n0 + tx] = ts[tx][ty + k * 8];
    }
}

// ---------------- block reductions ----------------
__device__ __forceinline__ float block_reduce_max(float v, float* red) {
    #pragma unroll
    for (int o = 16; o > 0; o >>= 1) v = fmaxf(v, __shfl_xor_sync(0xffffffffu, v, o));
    int wid = threadIdx.x >> 5, lid = threadIdx.x & 31;
    if (lid == 0) red[wid] = v;
    __syncthreads();
    if (wid == 0) {
        v = (lid < 8) ? red[lid] : -1e30f;
        #pragma unroll
        for (int o = 4; o > 0; o >>= 1) v = fmaxf(v, __shfl_xor_sync(0xffffffffu, v, o));
        if (lid == 0) red[0] = v;
    }
    __syncthreads();
    float r = red[0];
    __syncthreads();
    return r;
}
__device__ __forceinline__ float block_reduce_sum(float v, float* red) {
    #pragma unroll
    for (int o = 16; o > 0; o >>= 1) v += __shfl_xor_sync(0xffffffffu, v, o);
    int wid = threadIdx.x >> 5, lid = threadIdx.x & 31;
    if (lid == 0) red[wid] = v;
    __syncthreads();
    if (wid == 0) {
        v = (lid < 8) ? red[lid] : 0.f;
        #pragma unroll
        for (int o = 4; o > 0; o >>= 1) v += __shfl_xor_sync(0xffffffffu, v, o);
        if (lid == 0) red[0] = v;
    }
    __syncthreads();
    float r = red[0];
    __syncthreads();
    return r;
}

// ---------------- softmax mix: fp32 in -> half S out (FMA-only exp) ----------------
// e2 = exp(max(v,0)-m2) with m2=max(m1,0) satisfies: e2 = (v>0) ? e1 : exp(-m2).
__global__ __launch_bounds__(256) void softmax_mix_kernel(
    const float* __restrict__ attn, half* __restrict__ S, const float* __restrict__ w_mix)
{
    __shared__ float e1s[4096];
    __shared__ float red[32];
    const float* p = attn + (size_t)blockIdx.x * 4096;
    half* q = S + (size_t)blockIdx.x * 4096;
    int tid = threadIdx.x;

    float lmax = -1e30f;
    for (int i = tid; i < 4096; i += 256) {
        float v = p[i];
        e1s[i] = v;
        lmax = fmaxf(lmax, v);
    }
    float m1 = block_reduce_max(lmax, red);
    float m2 = fmaxf(m1, 0.f);
    float Cneg = fast_exp(-m2);

    float z1 = 0.f, z2p = 0.f, nneg = 0.f;
    for (int i = tid; i < 4096; i += 256) {
        float v = e1s[i];
        float e1 = fast_exp(v - m1);
        bool pos = v > 0.f;
        z1 += e1;
        if (pos) z2p += e1; else nneg += 1.f;
        e1s[i] = pos ? e1 : -e1;     // sign encodes (v>0)
    }
    float Z1 = block_reduce_sum(z1, red);
    float Z2 = block_reduce_sum(z2p, red) + block_reduce_sum(nneg, red) * Cneg;

    float ew0 = fast_exp(w_mix[0]), ew1 = fast_exp(w_mix[1]);
    float inv = 1.f / (ew0 + ew1);
    float iz1 = (ew0 * inv) / Z1;
    float iz2 = (ew1 * inv) / Z2;
    float Cn2 = Cneg * iz2;

    float za = 0.f;
    for (int i = tid; i < 4096; i += 256) {
        float se = e1s[i];
        float e1 = fabsf(se);
        float A = (se > 0.f) ? e1 * (iz1 + iz2) : fmaf(e1, iz1, Cn2);
        float e = fast_exp(A);   // A in (0,1]
        e1s[i] = e;
        za += e;
    }
    float ZA = block_reduce_sum(za, red);
    float izA = 1.f / ZA;
    for (int i = tid; i < 4096; i += 256)
        q[i] = __float2half_rn(e1s[i] * izA);
}

// ---------------- finalize: out = stdT * mvn(content) + meanT ----------------
__global__ __launch_bounds__(256) void finalize_kernel(
    const float* __restrict__ content, const float* __restrict__ meanT,
    const float* __restrict__ stdT, float* __restrict__ out)
{
    __shared__ float red[32];
    int c = blockIdx.x, b = blockIdx.y;
    size_t off = ((size_t)b * 512 + c) * 4096;
    const float* x = content + off;
    int tid = threadIdx.x;

    float s = 0.f, ss = 0.f;
    for (int i = tid; i < 4096; i += 256) {
        float v = x[i];
        s += v; ss += v * v;
    }
    s = block_reduce_sum(s, red);
    ss = block_reduce_sum(ss, red);
    float mu = s * (1.f / 4096.f);
    float var = (ss - 4096.f * mu * mu) * (1.f / 4095.f);
    float rstd = rsqrtf(var + 1e-5f);

    for (int i = tid; i < 4096; i += 256)
        out[off + i] = stdT[off + i] * ((x[i] - mu) * rstd) + meanT[off + i];
}

// ---------------- launch ----------------
extern "C" void kernel_launch(void* const* d_in, const int* in_sizes, int n_in,
                              void* d_out, int out_size)
{
    const float* content     = (const float*)d_in[0];
    const float* style       = (const float*)d_in[1];
    const float* content_key = (const float*)d_in[2];
    const float* style_key   = (const float*)d_in[3];
    const float* f_w = (const float*)d_in[4];
    const float* f_b = (const float*)d_in[5];
    const float* g_w = (const float*)d_in[6];
    const float* g_b = (const float*)d_in[7];
    const float* h_w = (const float*)d_in[8];
    const float* h_b = (const float*)d_in[9];
    const float* w_mix = (const float*)d_in[10];
    float* out = (float*)d_out;

    typedef __nv_bfloat16 bf16;
    void *p;
    cudaGetSymbolAddress(&p, g_attn4);  float* attn = (float*)p;
    cudaGetSymbolAddress(&p, g_S4);     half*  S    = (half*)p;
    cudaGetSymbolAddress(&p, g_xth4);   bf16*  XTh  = (bf16*)p;
    cudaGetSymbolAddress(&p, g_xtl4);   bf16*  XTl  = (bf16*)p;
    cudaGetSymbolAddress(&p, g_wh4);    bf16*  Wh   = (bf16*)p;
    cudaGetSymbolAddress(&p, g_wl4);    bf16*  Wl   = (bf16*)p;
    cudaGetSymbolAddress(&p, g_Fh4);    bf16*  Fh   = (bf16*)p;
    cudaGetSymbolAddress(&p, g_Fl4);    bf16*  Fl   = (bf16*)p;
    cudaGetSymbolAddress(&p, g_Gh4);    bf16*  Gh   = (bf16*)p;
    cudaGetSymbolAddress(&p, g_Gl4);    bf16*  Gl   = (bf16*)p;
    cudaGetSymbolAddress(&p, g_HmT4);   float* HmT  = (float*)p;
    cudaGetSymbolAddress(&p, g_Hcat4);  half*  Hcat = (half*)p;
    cudaGetSymbolAddress(&p, g_Ccat4);  float* Ccat = (float*)p;
    cudaGetSymbolAddress(&p, g_meanT4); float* meanT= (float*)p;
    cudaGetSymbolAddress(&p, g_stdT4);  float* stdT = (float*)p;

    const size_t XN = 4ull * 4096 * 512;
    const size_t WN = 512ull * 512;

    const int SM3 = 2 * 4 * (128 * 80);    // 81920  (TERMS=3, KCH=32)
    const int SM1 = 2 * 2 * (128 * 144);   // 73728  (TERMS=1, KCH=64)
    cudaFuncSetAttribute((gemm16<bf16,3,32,1,1>), cudaFuncAttributeMaxDynamicSharedMemorySize, SM3);
    cudaFuncSetAttribute((gemm16<bf16,3,32,0,1>), cudaFuncAttributeMaxDynamicSharedMemorySize, SM3);
    cudaFuncSetAttribute((gemm16<bf16,3,32,0,0>), cudaFuncAttributeMaxDynamicSharedMemorySize, SM3);
    cudaFuncSetAttribute((gemm16<half,1,64,0,0>), cudaFuncAttributeMaxDynamicSharedMemorySize, SM1);

    // 1) transpose+split inputs -> XT hi/lo bf16 [b][4096][512]
    transpose_split<<<dim3(128, 16, 4), dim3(32, 8)>>>(content_key, XTh + 0 * XN, XTl + 0 * XN);
    transpose_split<<<dim3(128, 16, 4), dim3(32, 8)>>>(style_key,   XTh + 1 * XN, XTl + 1 * XN);
    transpose_split<<<dim3(128, 16, 4), dim3(32, 8)>>>(style,       XTh + 2 * XN, XTl + 2 * XN);
    weight_split<<<dim3(1024), 256>>>(f_w, Wh + 0 * WN, Wl + 0 * WN, 262144);
    weight_split<<<dim3(1024), 256>>>(g_w, Wh + 1 * WN, Wl + 1 * WN, 262144);
    weight_split<<<dim3(1024), 256>>>(h_w, Wh + 2 * WN, Wl + 2 * WN, 262144);

    // 2) convs (bf16x3): F,G -> hi/lo bf16; H -> fp32
    gemm16<bf16,3,32,1,1><<<dim3(4, 32, 4), 256, SM3>>>(XTh + 0 * XN, XTl + 0 * XN,
        Wh + 0 * WN, Wl + 0 * WN, f_b, nullptr, Fh, Fl, 4096, 512, 512, 4096ull * 512, 0);
    gemm16<bf16,3,32,1,1><<<dim3(4, 32, 4), 256, SM3>>>(XTh + 1 * XN, XTl + 1 * XN,
        Wh + 1 * WN, Wl + 1 * WN, g_b, nullptr, Gh, Gl, 4096, 512, 512, 4096ull * 512, 0);
    gemm16<bf16,3,32,0,1><<<dim3(4, 32, 4), 256, SM3>>>(XTh + 2 * XN, XTl + 2 * XN,
        Wh + 2 * WN, Wl + 2 * WN, h_b, HmT, nullptr, nullptr, 4096, 512, 512, 4096ull * 512, 0);

    // 3) Hcat half [b][1024][4096] = [H[c][n] ; H^2]
    transpose_sq_half<<<dim3(16, 128, 4), dim3(32, 8)>>>(HmT, Hcat);

    // 4) attention logits (bf16x3, ~fp32 quality)
    gemm16<bf16,3,32,0,0><<<dim3(32, 32, 4), 256, SM3>>>(Fh, Fl, Gh, Gl, nullptr,
        attn, nullptr, nullptr, 4096, 4096, 512, 4096ull * 512, 4096ull * 512);

    // 5) triple-softmax mix -> S half
    softmax_mix_kernel<<<16384, 256>>>(attn, S, w_mix);

    // 6) mean/second GEMM (fp16, KCH=64): Ccat[n][1024] = S[n][m] * Hcat[cc][m]
    gemm16<half,1,64,0,0><<<dim3(8, 32, 4), 256, SM1>>>(S, nullptr, Hcat, nullptr, nullptr,
        Ccat, nullptr, nullptr, 4096, 1024, 4096, 4096ull * 4096, 1024ull * 4096);

    // 7) Ccat -> meanT/stdT [b][c][n]
    meanstd_transpose<<<dim3(16, 128, 4), dim3(32, 8)>>>(Ccat, meanT, stdT);

    // 8) finalize
    finalize_kernel<<<dim3(512, 4), 256>>>(content, meanT, stdT, out);
}